// round 3
// baseline (speedup 1.0000x reference)
#include <cuda_runtime.h>
#include <math.h>

#define OUTSZ 260
#define IMGW  2048
#define IMGH  2048
#define TAPS  6
#define NTHREADS 384
#define NBOX  10

struct __align__(16) Tap6 {
    float w[TAPS];
    int   j[TAPS];
};

__device__ Tap6 g_tapv[NBOX][OUTSZ];   // vertical: j = absolute image row
__device__ Tap6 g_taph[NBOX][OUTSZ];   // horizontal: j = crop-local float index (x*3), w includes validity
__device__ int  g_gbeg[NBOX];          // x0*3 (first needed float in an image row)
__device__ int  g_cw3[NBOX];           // cw*3

// Lanczos3 weights for 6 integer-spaced taps around src (frac in [0,1)):
//   d_a = frac + (2 - a),  sin(pi*d_a) = (-1)^a sin(pi*frac)
//   sin(pi*d_a/3) via angle addition with fixed constants.
__device__ __forceinline__ void lanczos6(float frac, float* w) {
    const float sn = sinpif(frac);
    const float su = sinpif(frac * (1.0f / 3.0f));
    const float cu = cospif(frac * (1.0f / 3.0f));
    const float R3 = 0.8660254037844386f;
    float s3[TAPS];
    s3[0] = fmaf(su, -0.5f,  cu *  R3);
    s3[1] = fmaf(su,  0.5f,  cu *  R3);
    s3[2] = su;
    s3[3] = fmaf(su,  0.5f,  cu * -R3);
    s3[4] = fmaf(su, -0.5f,  cu * -R3);
    s3[5] = -su;
    const float C = 3.0f / (3.14159265358979323846f * 3.14159265358979323846f);
#pragma unroll
    for (int a = 0; a < TAPS; a++) {
        float d = frac + (float)(2 - a);
        float sgn = (a & 1) ? -sn : sn;
        float val = sgn * s3[a] * C / (d * d);
        w[a] = (fabsf(d) < 1e-8f) ? 1.0f : val;
    }
}

__global__ void precompute_taps(const float* __restrict__ scores,
                                const float* __restrict__ boxes) {
    const int box = blockIdx.x;     // 0..9
    const int p   = threadIdx.x;    // 0..259

    const float b0 = boxes[box * 4 + 0];
    const float b1 = boxes[box * 4 + 1];
    const float b2 = boxes[box * 4 + 2];
    const float b3 = boxes[box * 4 + 3];
    // XLA f32->s32 convert truncates toward zero; values are non-negative here.
    const int y0 = (int)(b0 * (float)IMGH);
    const int x0 = (int)(b1 * (float)IMGW);
    const int y1 = (int)(b2 * (float)IMGH);
    const int x1 = (int)(b3 * (float)IMGW);
    const int ch = max(y1 - y0, 1);
    const int cw = max(x1 - x0, 1);

    const bool valid = (scores[0] >= 0.8f) && (scores[box] >= 0.8f) &&
                       (b1 >= 0.0f) && (b3 <= 1.0f);

    // vertical taps for output row p
    {
        const float src = ((float)p + 0.5f) * ((float)ch / (float)OUTSZ) - 0.5f;
        const float f = floorf(src);
        const int base = (int)f - 2;
        Tap6 t;
        lanczos6(src - f, t.w);
        float s = t.w[0] + t.w[1] + t.w[2] + t.w[3] + t.w[4] + t.w[5];
        float inv = 1.0f / s;
#pragma unroll
        for (int a = 0; a < TAPS; a++) {
            t.w[a] *= inv;
            t.j[a] = min(max(base + a, 0), ch - 1) + y0;
        }
        g_tapv[box][p] = t;
    }

    // horizontal taps for output col p (same index space)
    {
        const float src = ((float)p + 0.5f) * ((float)cw / (float)OUTSZ) - 0.5f;
        const float f = floorf(src);
        const int base = (int)f - 2;
        Tap6 t;
        lanczos6(src - f, t.w);
        float s = t.w[0] + t.w[1] + t.w[2] + t.w[3] + t.w[4] + t.w[5];
        float inv = valid ? (1.0f / s) : 0.0f;   // fold validity mask
#pragma unroll
        for (int b = 0; b < TAPS; b++) {
            t.w[b] *= inv;
            t.j[b] = min(max(base + b, 0), cw - 1) * 3;
        }
        g_taph[box][p] = t;
    }

    if (p == 0) {
        g_gbeg[box] = x0 * 3;
        g_cw3[box]  = cw * 3;
    }
}

__global__ __launch_bounds__(NTHREADS, 4)
void crop_resize_kernel(const float* __restrict__ img,
                        float* __restrict__ out) {
    const int p   = blockIdx.x;   // output row 0..259
    const int box = blockIdx.y;   // 0..9

    // ---- load vertical taps (broadcast 48B) ----
    const float4* tv4 = (const float4*)&g_tapv[box][p];
    const float4 v0 = tv4[0];             // w0..w3
    const float4 v1 = tv4[1];             // w4, w5, j0, j1
    const float4 v2 = tv4[2];             // j2..j5
    float wh[TAPS] = {v0.x, v0.y, v0.z, v0.w, v1.x, v1.y};
    const float4* rowp[TAPS];
    {
        int r0 = __float_as_int(v1.z), r1 = __float_as_int(v1.w);
        int r2 = __float_as_int(v2.x), r3 = __float_as_int(v2.y);
        int r4 = __float_as_int(v2.z), r5 = __float_as_int(v2.w);
        rowp[0] = (const float4*)(img + (size_t)r0 * (IMGW * 3));
        rowp[1] = (const float4*)(img + (size_t)r1 * (IMGW * 3));
        rowp[2] = (const float4*)(img + (size_t)r2 * (IMGW * 3));
        rowp[3] = (const float4*)(img + (size_t)r3 * (IMGW * 3));
        rowp[4] = (const float4*)(img + (size_t)r4 * (IMGW * 3));
        rowp[5] = (const float4*)(img + (size_t)r5 * (IMGW * 3));
    }
    const int gbeg = g_gbeg[box];
    const int gend = gbeg + g_cw3[box];
    const int gb4  = gbeg & ~3;

    // ---- Stage A: vertical combine into shared row buffer (float4 LDG) ----
    extern __shared__ float smem_raw[];
    float* rc = smem_raw + 4;             // 4-float front slack
#pragma unroll 1
    for (int g = gb4 + 4 * threadIdx.x; g < gend; g += 4 * NTHREADS) {
        const int g4 = g >> 2;
        float4 acc = make_float4(0.f, 0.f, 0.f, 0.f);
#pragma unroll
        for (int a = 0; a < TAPS; a++) {
            float4 v = __ldg(rowp[a] + g4);
            acc.x = fmaf(wh[a], v.x, acc.x);
            acc.y = fmaf(wh[a], v.y, acc.y);
            acc.z = fmaf(wh[a], v.z, acc.z);
            acc.w = fmaf(wh[a], v.w, acc.w);
        }
        const int s = g - gbeg;
        rc[s + 0] = acc.x;
        rc[s + 1] = acc.y;
        rc[s + 2] = acc.z;
        rc[s + 3] = acc.w;
    }
    __syncthreads();

    // ---- Stage B: horizontal combine from shared memory ----
    for (int q = threadIdx.x; q < OUTSZ; q += NTHREADS) {
        const float4* th4 = (const float4*)&g_taph[box][q];
        const float4 h0 = th4[0];
        const float4 h1 = th4[1];
        const float4 h2 = th4[2];
        const float w0 = h0.x, w1 = h0.y, w2 = h0.z, w3 = h0.w, w4 = h1.x, w5 = h1.y;
        const int j0 = __float_as_int(h1.z), j1 = __float_as_int(h1.w);
        const int j2 = __float_as_int(h2.x), j3 = __float_as_int(h2.y);
        const int j4 = __float_as_int(h2.z), j5 = __float_as_int(h2.w);

        float o0, o1, o2;
        o0 = w0 * rc[j0 + 0]; o1 = w0 * rc[j0 + 1]; o2 = w0 * rc[j0 + 2];
        o0 = fmaf(w1, rc[j1 + 0], o0); o1 = fmaf(w1, rc[j1 + 1], o1); o2 = fmaf(w1, rc[j1 + 2], o2);
        o0 = fmaf(w2, rc[j2 + 0], o0); o1 = fmaf(w2, rc[j2 + 1], o1); o2 = fmaf(w2, rc[j2 + 2], o2);
        o0 = fmaf(w3, rc[j3 + 0], o0); o1 = fmaf(w3, rc[j3 + 1], o1); o2 = fmaf(w3, rc[j3 + 2], o2);
        o0 = fmaf(w4, rc[j4 + 0], o0); o1 = fmaf(w4, rc[j4 + 1], o1); o2 = fmaf(w4, rc[j4 + 2], o2);
        o0 = fmaf(w5, rc[j5 + 0], o0); o1 = fmaf(w5, rc[j5 + 1], o1); o2 = fmaf(w5, rc[j5 + 2], o2);

        size_t oidx = (((size_t)box * OUTSZ + p) * OUTSZ + q) * 3;
        out[oidx + 0] = o0;
        out[oidx + 1] = o1;
        out[oidx + 2] = o2;
    }
}

extern "C" void kernel_launch(void* const* d_in, const int* in_sizes, int n_in,
                              void* d_out, int out_size) {
    const float* scores = (const float*)d_in[0];   // (100,)
    const float* boxes  = (const float*)d_in[1];   // (100,4)
    const float* img    = (const float*)d_in[2];   // (1,2048,2048,3)
    float* out = (float*)d_out;                    // (10,260,260,3)

    precompute_taps<<<NBOX, OUTSZ>>>(scores, boxes);

    dim3 grid(OUTSZ, NBOX);
    dim3 block(NTHREADS);
    size_t smem = (size_t)(4 + IMGW * 3 + 4) * sizeof(float);  // ~24.6 KB
    crop_resize_kernel<<<grid, block, smem>>>(img, out);
}